// round 15
// baseline (speedup 1.0000x reference)
#include <cuda_runtime.h>
#include <cuda_bf16.h>
#include <cstdint>

#define BB 4
#define HH 16
#define LL 2048
#define DM 1024
#define DHEAD 64
#define NZ (BB * HH)

// Scratch (__device__ globals; allocation-free rule)
__device__ float g_Q[(size_t)NZ * LL * DHEAD];
__device__ float g_K[(size_t)NZ * LL * DHEAD];
__device__ float g_VT[(size_t)NZ * DHEAD * LL];   // V^T fp32 [z][e][kv]
__device__ float g_ctx[(size_t)BB * LL * (HH * DHEAD)];

// ===========================================================================
// tf32 mma.sync (m16n8k8) + bf16 mma.sync (m16n8k16) helpers
// ===========================================================================
__device__ __forceinline__ void mma_tf32(float* c,
                                         uint32_t a0, uint32_t a1, uint32_t a2, uint32_t a3,
                                         uint32_t b0, uint32_t b1)
{
    asm volatile(
        "mma.sync.aligned.m16n8k8.row.col.f32.tf32.tf32.f32 "
        "{%0,%1,%2,%3}, {%4,%5,%6,%7}, {%8,%9}, {%0,%1,%2,%3};"
        : "+f"(c[0]), "+f"(c[1]), "+f"(c[2]), "+f"(c[3])
        : "r"(a0), "r"(a1), "r"(a2), "r"(a3), "r"(b0), "r"(b1));
}
__device__ __forceinline__ uint32_t f2tf32(float x)
{
    uint32_t r;
    asm("cvt.rna.tf32.f32 %0, %1;" : "=r"(r) : "f"(x));
    return r;
}
__device__ __forceinline__ void mma_bf16(float* c,
                                         uint32_t a0, uint32_t a1, uint32_t a2, uint32_t a3,
                                         uint32_t b0, uint32_t b1)
{
    asm volatile(
        "mma.sync.aligned.m16n8k16.row.col.f32.bf16.bf16.f32 "
        "{%0,%1,%2,%3}, {%4,%5,%6,%7}, {%8,%9}, {%0,%1,%2,%3};"
        : "+f"(c[0]), "+f"(c[1]), "+f"(c[2]), "+f"(c[3])
        : "r"(a0), "r"(a1), "r"(a2), "r"(a3), "r"(b0), "r"(b1));
}
__device__ __forceinline__ void mma3(float* c,
                                     const uint32_t* ah, const uint32_t* al,
                                     const uint32_t* bh, const uint32_t* bl)
{
    mma_bf16(c, ah[0], ah[1], ah[2], ah[3], bh[0], bh[1]);
    mma_bf16(c, ah[0], ah[1], ah[2], ah[3], bl[0], bl[1]);
    mma_bf16(c, al[0], al[1], al[2], al[3], bh[0], bh[1]);
}
__device__ __forceinline__ void split_pair(float x, float y, uint32_t& h, uint32_t& l)
{
    __nv_bfloat16 hx = __float2bfloat16(x);
    __nv_bfloat16 hy = __float2bfloat16(y);
    __nv_bfloat162 hp = __halves2bfloat162(hx, hy);
    __nv_bfloat162 lp = __halves2bfloat162(__float2bfloat16(x - __bfloat162float(hx)),
                                           __float2bfloat16(y - __bfloat162float(hy)));
    h = *(uint32_t*)&hp;
    l = *(uint32_t*)&lp;
}
__device__ __forceinline__ void split_one(float x, __nv_bfloat16& h, __nv_bfloat16& l)
{
    h = __float2bfloat16(x);
    l = __float2bfloat16(x - __bfloat162float(h));
}

// Paired-k store helper: 4 consecutive k values starting at c (c%4==0) go to
// positions base + (c&7? 1:0) + {0,2,4,6}  within their k8 block.
__device__ __forceinline__ void store_k4_paired(uint32_t* row, int c,
                                                float x, float y, float zv, float w)
{
    int base = (c & ~7) + ((c & 4) ? 1 : 0);
    row[base + 0] = f2tf32(x);
    row[base + 2] = f2tf32(y);
    row[base + 4] = f2tf32(zv);
    row[base + 6] = f2tf32(w);
}

// ===========================================================================
// score_mma: S[z,i,j] = 0.125 * Q·K^T   (tf32, paired-k smem, LDS.64 frags)
// CTA 128x128, 512 threads / 16 warps (4x4), warp tile 32x32. 8 k8-steps.
// grid=(16 j, 16 i, 64 z), smem 69632 B
// ===========================================================================
__global__ __launch_bounds__(512) void score_mma(const float* __restrict__ Qp,
                                                 const float* __restrict__ Kp,
                                                 float* __restrict__ Sout)
{
    extern __shared__ char smraw[];
    uint32_t* Qs = (uint32_t*)smraw;        // [128][68], paired-k
    uint32_t* Ks = Qs + 128 * 68;           // [128][68], paired-k
    float* Ssm = (float*)smraw;             // epilogue reuse [128][132]

    const int tid = threadIdx.x, wid = tid >> 5, lane = tid & 31;
    const int wm = (wid >> 2) * 32, wn = (wid & 3) * 32;
    const int z = blockIdx.z, i0 = blockIdx.y * 128, j0 = blockIdx.x * 128;
    const float* Q = Qp + (size_t)z * LL * DHEAD;
    const float* K = Kp + (size_t)z * LL * DHEAD;

    #pragma unroll
    for (int t = 0; t < 4; t++) {
        int v = tid + t * 512;
        int r = v >> 4, c = (v & 15) * 4;
        float4 qv = *(const float4*)&Q[(size_t)(i0 + r) * DHEAD + c];
        store_k4_paired(&Qs[r * 68], c, qv.x, qv.y, qv.z, qv.w);
        float4 kv = *(const float4*)&K[(size_t)(j0 + r) * DHEAD + c];
        store_k4_paired(&Ks[r * 68], c, kv.x, kv.y, kv.z, kv.w);
    }
    __syncthreads();

    float acc[2][4][4] = {};
    const int fr = lane >> 2, fc = lane & 3;

    #pragma unroll
    for (int ks = 0; ks < 8; ks++) {
        const int k0 = ks * 8;
        uint2 bv[4];
        #pragma unroll
        for (int jn = 0; jn < 4; jn++) {
            int n = wn + jn * 8 + fr;
            bv[jn] = *(uint2*)&Ks[n * 68 + k0 + 2 * fc];
        }
        #pragma unroll
        for (int im = 0; im < 2; im++) {
            int m = wm + im * 16 + fr;
            uint2 av0 = *(uint2*)&Qs[m * 68 + k0 + 2 * fc];        // a0, a2
            uint2 av1 = *(uint2*)&Qs[(m + 8) * 68 + k0 + 2 * fc];  // a1, a3
            #pragma unroll
            for (int jn = 0; jn < 4; jn++)
                mma_tf32(acc[im][jn], av0.x, av1.x, av0.y, av1.y, bv[jn].x, bv[jn].y);
        }
    }
    __syncthreads();

    const int qr = lane >> 2, qc = (lane & 3) * 2;
    #pragma unroll
    for (int im = 0; im < 2; im++) {
        int row = wm + im * 16 + qr;
        #pragma unroll
        for (int jn = 0; jn < 4; jn++) {
            int col = wn + jn * 8 + qc;
            *(float2*)&Ssm[row * 132 + col] =
                make_float2(acc[im][jn][0] * 0.125f, acc[im][jn][1] * 0.125f);
            *(float2*)&Ssm[(row + 8) * 132 + col] =
                make_float2(acc[im][jn][2] * 0.125f, acc[im][jn][3] * 0.125f);
        }
    }
    __syncthreads();

    float* S = Sout + (size_t)z * LL * LL;
    #pragma unroll
    for (int t = 0; t < 8; t++) {
        int v = tid + t * 512;
        int r = v >> 5, c = (v & 31) * 4;
        *(float4*)&S[(size_t)(i0 + r) * LL + j0 + c] = *(float4*)&Ssm[r * 132 + c];
    }
}

// ===========================================================================
// ctx_mma: C[z] = attn[z](2048x2048) @ V[z](2048x64)   (tf32, paired-k)
// CTA 128x64, 512 threads / 16 warps (8x2), warp tile 16x32. kv chunks of 64.
// grid=(16 i, 64 z), smem 52224 B
// ===========================================================================
__global__ __launch_bounds__(512) void ctx_mma(const float* __restrict__ Sm,
                                               const float* __restrict__ VT,
                                               float* __restrict__ Ctx)
{
    extern __shared__ char smraw[];
    uint32_t* As = (uint32_t*)smraw;        // [128][68], paired-k
    uint32_t* Ts = As + 128 * 68;           // V^T chunk [64][68], paired-k
    float* Cs = (float*)smraw;              // epilogue reuse [128][68]

    const int tid = threadIdx.x, wid = tid >> 5, lane = tid & 31;
    const int wm = (wid >> 1) * 16, wn = (wid & 1) * 32;
    const int z = blockIdx.y, b = z >> 4, h = z & 15;
    const int i0 = blockIdx.x * 128;
    const float* A = Sm + (size_t)z * LL * LL;

    const int fr = lane >> 2, fc = lane & 3;
    float acc[4][4] = {};

    for (int c = 0; c < 32; c++) {
        const int kv0 = c * 64;
        #pragma unroll
        for (int t = 0; t < 4; t++) {
            int v = tid + t * 512;
            int r = v >> 4, cc = (v & 15) * 4;
            float4 av = *(const float4*)&A[(size_t)(i0 + r) * LL + kv0 + cc];
            store_k4_paired(&As[r * 68], cc, av.x, av.y, av.z, av.w);
        }
        #pragma unroll
        for (int t = 0; t < 2; t++) {
            int v = tid + t * 512;
            int e = v >> 4, kp = (v & 15) * 4;
            float4 vv = *(const float4*)&VT[((size_t)z * DHEAD + e) * LL + kv0 + kp];
            store_k4_paired(&Ts[e * 68], kp, vv.x, vv.y, vv.z, vv.w);
        }
        __syncthreads();

        #pragma unroll
        for (int ks = 0; ks < 8; ks++) {
            const int k0 = ks * 8;
            uint2 bv[4];
            #pragma unroll
            for (int jn = 0; jn < 4; jn++) {
                int n = wn + jn * 8 + fr;
                bv[jn] = *(uint2*)&Ts[n * 68 + k0 + 2 * fc];
            }
            int m = wm + fr;
            uint2 av0 = *(uint2*)&As[m * 68 + k0 + 2 * fc];
            uint2 av1 = *(uint2*)&As[(m + 8) * 68 + k0 + 2 * fc];
            #pragma unroll
            for (int jn = 0; jn < 4; jn++)
                mma_tf32(acc[jn], av0.x, av1.x, av0.y, av1.y, bv[jn].x, bv[jn].y);
        }
        __syncthreads();
    }

    const int qr = lane >> 2, qc = (lane & 3) * 2;
    {
        int row = wm + qr;
        #pragma unroll
        for (int jn = 0; jn < 4; jn++) {
            int col = wn + jn * 8 + qc;
            *(float2*)&Cs[row * 68 + col] = make_float2(acc[jn][0], acc[jn][1]);
            *(float2*)&Cs[(row + 8) * 68 + col] = make_float2(acc[jn][2], acc[jn][3]);
        }
    }
    __syncthreads();
    #pragma unroll
    for (int t = 0; t < 4; t++) {
        int v = tid + t * 512;
        int r = v >> 4, cc = (v & 15) * 4;
        *(float4*)&Ctx[((size_t)b * LL + i0 + r) * (HH * DHEAD) + h * DHEAD + cc] =
            *(float4*)&Cs[r * 68 + cc];
    }
}

// ===========================================================================
// proj_mma: Out[b,h,s,e] = sum_d X[b,s,d] W[h,d,e]   (split-bf16, R12-exact)
// mode 0: float row-major Q/K.  mode 1: V^T fp32 [z][e][kv].
// ===========================================================================
__global__ __launch_bounds__(256) void proj_mma(const float* __restrict__ X,
                                                const float* __restrict__ W,
                                                float* __restrict__ OutF,
                                                float* __restrict__ OutT,
                                                int mode)
{
    extern __shared__ char smraw[];
    __nv_bfloat16* XH = (__nv_bfloat16*)smraw;     // [128][40]
    __nv_bfloat16* XL = XH + 128 * 40;
    __nv_bfloat16* TH = XL + 128 * 40;             // W^T [64 e][40]
    __nv_bfloat16* TL = TH + 64 * 40;
    float* Cs = (float*)smraw;                     // [128][68]

    const int tid = threadIdx.x, wid = tid >> 5, lane = tid & 31;
    const int wm = (wid >> 1) * 32, wn = (wid & 1) * 32;
    const int b = blockIdx.z, hh = blockIdx.y, i0 = blockIdx.x * 128;
    const int z = b * HH + hh;
    const float* A  = X + (size_t)b * LL * DM;
    const float* Bw = W + (size_t)hh * DM * DHEAD;

    const int qr = lane >> 2, qc = (lane & 3) * 2;
    float acc[2][4][4] = {};

    for (int c = 0; c < 32; c++) {
        const int k0g = c * 32;
        #pragma unroll
        for (int t = 0; t < 4; t++) {
            int v = tid + t * 256;
            int r = v >> 3, cc = (v & 7) * 4;
            float4 xv = *(const float4*)&A[(size_t)(i0 + r) * DM + k0g + cc];
            uint32_t h0, l0, h1, l1;
            split_pair(xv.x, xv.y, h0, l0);
            split_pair(xv.z, xv.w, h1, l1);
            *(uint32_t*)&XH[r * 40 + cc] = h0; *(uint32_t*)&XH[r * 40 + cc + 2] = h1;
            *(uint32_t*)&XL[r * 40 + cc] = l0; *(uint32_t*)&XL[r * 40 + cc + 2] = l1;
        }
        #pragma unroll
        for (int t = 0; t < 2; t++) {
            int v = tid + t * 256;
            int r = v >> 4, cc = (v & 15) * 4;
            float4 wv = *(const float4*)&Bw[(size_t)(k0g + r) * DHEAD + cc];
            float vals[4] = {wv.x, wv.y, wv.z, wv.w};
            #pragma unroll
            for (int jj = 0; jj < 4; jj++) {
                __nv_bfloat16 hh2, ll;
                split_one(vals[jj], hh2, ll);
                TH[(cc + jj) * 40 + r] = hh2;
                TL[(cc + jj) * 40 + r] = ll;
            }
        }
        __syncthreads();

        #pragma unroll
        for (int ks = 0; ks < 2; ks++) {
            const int k0 = ks * 16;
            uint32_t bh[4][2], bl[4][2];
            #pragma unroll
            for (int jn = 0; jn < 4; jn++) {
                int n = wn + jn * 8 + qr;
                bh[jn][0] = *(uint32_t*)&TH[n * 40 + k0 + qc];
                bh[jn][1] = *(uint32_t*)&TH[n * 40 + k0 + 8 + qc];
                bl[jn][0] = *(uint32_t*)&TL[n * 40 + k0 + qc];
                bl[jn][1] = *(uint32_t*)&TL[n * 40 + k0 + 8 + qc];
            }
            #pragma unroll
            for (int im = 0; im < 2; im++) {
                int m = wm + im * 16 + qr;
                uint32_t ah[4], al[4];
                ah[0] = *(uint32_t*)&XH[m * 40 + k0 + qc];
                ah[1] = *(uint32_t*)&XH[(m + 8) * 40 + k0 + qc];
                ah[2] = *(uint32_t*)&XH[m * 40 + k0 + 8 + qc];
                ah[3] = *(uint32_t*)&XH[(m + 8) * 40 + k0 + 8 + qc];
                al[0] = *(uint32_t*)&XL[m * 40 + k0 + qc];
                al[1] = *(uint32_t*)&XL[(m + 8) * 40 + k0 + qc];
                al[2] = *(uint32_t*)&XL[m * 40 + k0 + 8 + qc];
                al[3] = *(uint32_t*)&XL[(m + 8) * 40 + k0 + 8 + qc];
                #pragma unroll
                for (int jn = 0; jn < 4; jn++)
                    mma3(acc[im][jn], ah, al, bh[jn], bl[jn]);
            }
        }
        __syncthreads();
    }

    #pragma unroll
    for (int im = 0; im < 2; im++) {
        int row = wm + im * 16 + qr;
        #pragma unroll
        for (int jn = 0; jn < 4; jn++) {
            int col = wn + jn * 8 + qc;
            *(float2*)&Cs[row * 68 + col] = make_float2(acc[im][jn][0], acc[im][jn][1]);
            *(float2*)&Cs[(row + 8) * 68 + col] = make_float2(acc[im][jn][2], acc[im][jn][3]);
        }
    }
    __syncthreads();

    if (mode == 0) {
        float* Out = OutF + ((size_t)z * LL + i0) * DHEAD;
        #pragma unroll
        for (int t = 0; t < 8; t++) {
            int v = tid + t * 256;
            int r = v >> 4, cc = (v & 15) * 4;
            *(float4*)&Out[(size_t)r * DHEAD + cc] = *(float4*)&Cs[r * 68 + cc];
        }
    } else {
        // V^T fp32: [z][e][kv]
        #pragma unroll
        for (int t = 0; t < 32; t++) {
            int v = tid + t * 256;
            int e = v >> 7, row = v & 127;
            OutT[((size_t)z * DHEAD + e) * LL + i0 + row] = Cs[row * 68 + e];
        }
    }
}

// ===========================================================================
// out_mma: Out(8192x1024) = Ctx(8192x1024) @ Wo(1024x1024)   (split-bf16)
// ===========================================================================
__global__ __launch_bounds__(256) void out_mma(const float* __restrict__ Ctx,
                                               const float* __restrict__ Wo,
                                               float* __restrict__ Out)
{
    extern __shared__ char smraw[];
    __nv_bfloat16* XH = (__nv_bfloat16*)smraw;     // [128][40]
    __nv_bfloat16* XL = XH + 128 * 40;
    __nv_bfloat16* TH = XL + 128 * 40;             // Wo^T [64 n][40]
    __nv_bfloat16* TL = TH + 64 * 40;
    float* Cs = (float*)smraw;

    const int tid = threadIdx.x, wid = tid >> 5, lane = tid & 31;
    const int wm = (wid >> 1) * 32, wn = (wid & 1) * 32;
    const int i0 = blockIdx.y * 128, j0 = blockIdx.x * 64;
    const int NN = HH * DHEAD;

    const int qr = lane >> 2, qc = (lane & 3) * 2;
    float acc[2][4][4] = {};

    for (int c = 0; c < 32; c++) {
        const int k0g = c * 32;
        #pragma unroll
        for (int t = 0; t < 4; t++) {
            int v = tid + t * 256;
            int r = v >> 3, cc = (v & 7) * 4;
            float4 xv = *(const float4*)&Ctx[(size_t)(i0 + r) * NN + k0g + cc];
            uint32_t h0, l0, h1, l1;
            split_pair(xv.x, xv.y, h0, l0);
            split_pair(xv.z, xv.w, h1, l1);
            *(uint32_t*)&XH[r * 40 + cc] = h0; *(uint32_t*)&XH[r * 40 + cc + 2] = h1;
            *(uint32_t*)&XL[r * 40 + cc] = l0; *(uint32_t*)&XL[r * 40 + cc + 2] = l1;
        }
        #pragma unroll
        for (int t = 0; t < 2; t++) {
            int v = tid + t * 256;
            int r = v >> 4, cc = (v & 15) * 4;
            float4 wv = *(const float4*)&Wo[(size_t)(k0g + r) * DM + j0 + cc];
            float vals[4] = {wv.x, wv.y, wv.z, wv.w};
            #pragma unroll
            for (int jj = 0; jj < 4; jj++) {
                __nv_bfloat16 hh, ll;
                split_one(vals[jj], hh, ll);
                TH[(cc + jj) * 40 + r] = hh;
                TL[(cc + jj) * 40 + r] = ll;
            }
        }
        __syncthreads();

        #pragma unroll
        for (int ks = 0; ks < 2; ks++) {
            const int k0 = ks * 16;
            uint32_t bh[4][2], bl[4][2];
            #pragma unroll
            for (int jn = 0; jn < 4; jn++) {
                int n = wn + jn * 8 + qr;
                bh[jn][0] = *(uint32_t*)&TH[n * 40 + k0 + qc];
                bh[jn][1] = *(uint32_t*)&TH[n * 40 + k0 + 8 + qc];
                bl[jn][0] = *(uint32_t*)&TL[n * 40 + k0 + qc];
                bl[jn][1] = *(uint32_t*)&TL[n * 40 + k0 + 8 + qc];
            }
            #pragma unroll
            for (int im = 0; im < 2; im++) {
                int m = wm + im * 16 + qr;
                uint32_t ah[4], al[4];
                ah[0] = *(uint32_t*)&XH[m * 40 + k0 + qc];
                ah[1] = *(uint32_t*)&XH[(m + 8) * 40 + k0 + qc];
                ah[2] = *(uint32_t*)&XH[m * 40 + k0 + 8 + qc];
                ah[3] = *(uint32_t*)&XH[(m + 8) * 40 + k0 + 8 + qc];
                al[0] = *(uint32_t*)&XL[m * 40 + k0 + qc];
                al[1] = *(uint32_t*)&XL[(m + 8) * 40 + k0 + qc];
                al[2] = *(uint32_t*)&XL[m * 40 + k0 + 8 + qc];
                al[3] = *(uint32_t*)&XL[(m + 8) * 40 + k0 + 8 + qc];
                #pragma unroll
                for (int jn = 0; jn < 4; jn++)
                    mma3(acc[im][jn], ah, al, bh[jn], bl[jn]);
            }
        }
        __syncthreads();
    }

    #pragma unroll
    for (int im = 0; im < 2; im++) {
        int row = wm + im * 16 + qr;
        #pragma unroll
        for (int jn = 0; jn < 4; jn++) {
            int col = wn + jn * 8 + qc;
            *(float2*)&Cs[row * 68 + col] = make_float2(acc[im][jn][0], acc[im][jn][1]);
            *(float2*)&Cs[(row + 8) * 68 + col] = make_float2(acc[im][jn][2], acc[im][jn][3]);
        }
    }
    __syncthreads();
    #pragma unroll
    for (int t = 0; t < 8; t++) {
        int v = tid + t * 256;
        int r = v >> 4, cc = (v & 15) * 4;
        *(float4*)&Out[(size_t)(i0 + r) * DM + j0 + cc] = *(float4*)&Cs[r * 68 + cc];
    }
}

// ===========================================================================
// Row softmax, 2048 elems, in place. grid=(131072), block=256
// ===========================================================================
__global__ __launch_bounds__(256) void softmax_kernel(float* __restrict__ S)
{
    float4* p4 = (float4*)(S + (size_t)blockIdx.x * LL);
    const int tid = threadIdx.x;
    const int warp = tid >> 5, lane = tid & 31;
    __shared__ float red[8];

    float4 v0 = p4[tid], v1 = p4[tid + 256];
    float m = fmaxf(fmaxf(fmaxf(v0.x, v0.y), fmaxf(v0.z, v0.w)),
                    fmaxf(fmaxf(v1.x, v1.y), fmaxf(v1.z, v1.w)));
    #pragma unroll
    for (int o = 16; o > 0; o >>= 1) m = fmaxf(m, __shfl_xor_sync(0xffffffffu, m, o));
    if (lane == 0) red[warp] = m;
    __syncthreads();
    if (tid < 8) {
        float t = red[tid];
        #pragma unroll
        for (int o = 4; o > 0; o >>= 1) t = fmaxf(t, __shfl_xor_sync(0xffu, t, o));
        if (tid == 0) red[0] = t;
    }
    __syncthreads();
    m = red[0];
    __syncthreads();

    v0.x = __expf(v0.x - m); v0.y = __expf(v0.y - m);
    v0.z = __expf(v0.z - m); v0.w = __expf(v0.w - m);
    v1.x = __expf(v1.x - m); v1.y = __expf(v1.y - m);
    v1.z = __expf(v1.z - m); v1.w = __expf(v1.w - m);
    float s = v0.x + v0.y + v0.z + v0.w + v1.x + v1.y + v1.z + v1.w;
    #pragma unroll
    for (int o = 16; o > 0; o >>= 1) s += __shfl_xor_sync(0xffffffffu, s, o);
    if (lane == 0) red[warp] = s;
    __syncthreads();
    if (tid < 8) {
        float t = red[tid];
        #pragma unroll
        for (int o = 4; o > 0; o >>= 1) t += __shfl_xor_sync(0xffu, t, o);
        if (tid == 0) red[0] = t;
    }
    __syncthreads();
    float inv = 1.0f / red[0];

    v0.x *= inv; v0.y *= inv; v0.z *= inv; v0.w *= inv;
    v1.x *= inv; v1.y *= inv; v1.z *= inv; v1.w *= inv;
    p4[tid] = v0; p4[tid + 256] = v1;
}

// ===========================================================================
extern "C" void kernel_launch(void* const* d_in, const int* in_sizes, int n_in,
                              void* d_out, int out_size)
{
    const float* q  = (const float*)d_in[0];
    const float* k  = (const float*)d_in[1];
    const float* v  = (const float*)d_in[2];
    const float* wq = (const float*)d_in[3];
    const float* wk = (const float*)d_in[4];
    const float* wv = (const float*)d_in[5];
    const float* wo = (const float*)d_in[6];

    float* out = (float*)d_out;
    const size_t OUT_ELEMS = (size_t)BB * LL * DM;

    float *gQ, *gK, *gVT, *gCtx;
    cudaGetSymbolAddress((void**)&gQ, g_Q);
    cudaGetSymbolAddress((void**)&gK, g_K);
    cudaGetSymbolAddress((void**)&gVT, g_VT);
    cudaGetSymbolAddress((void**)&gCtx, g_ctx);

    float* attn = out + OUT_ELEMS;

    const int proj_smem = 34816;
    cudaFuncSetAttribute(proj_mma, cudaFuncAttributeMaxDynamicSharedMemorySize, proj_smem);
    proj_mma<<<dim3(LL / 128, HH, BB), dim3(256), proj_smem>>>(q, wq, gQ, nullptr, 0);
    proj_mma<<<dim3(LL / 128, HH, BB), dim3(256), proj_smem>>>(k, wk, gK, nullptr, 0);
    proj_mma<<<dim3(LL / 128, HH, BB), dim3(256), proj_smem>>>(v, wv, nullptr, gVT, 1);

    const int score_smem = 69632;
    cudaFuncSetAttribute(score_mma, cudaFuncAttributeMaxDynamicSharedMemorySize, score_smem);
    score_mma<<<dim3(LL / 128, LL / 128, NZ), dim3(512), score_smem>>>(gQ, gK, attn);

    softmax_kernel<<<dim3(NZ * LL), dim3(256)>>>(attn);

    const int ctx_smem = 52224;
    cudaFuncSetAttribute(ctx_mma, cudaFuncAttributeMaxDynamicSharedMemorySize, ctx_smem);
    ctx_mma<<<dim3(LL / 128, NZ), dim3(512), ctx_smem>>>(attn, gVT, gCtx);

    const int out_smem = 34816;
    cudaFuncSetAttribute(out_mma, cudaFuncAttributeMaxDynamicSharedMemorySize, out_smem);
    out_mma<<<dim3(DM / 64, (BB * LL) / 128), dim3(256), out_smem>>>(gCtx, wo, out);
}

// round 16
// speedup vs baseline: 1.1209x; 1.1209x over previous
#include <cuda_runtime.h>
#include <cuda_bf16.h>
#include <cstdint>

#define BB 4
#define HH 16
#define LL 2048
#define DM 1024
#define DHEAD 64
#define NZ (BB * HH)

// Scratch (__device__ globals; allocation-free rule)
__device__ float g_Q[(size_t)NZ * LL * DHEAD];
__device__ float g_K[(size_t)NZ * LL * DHEAD];
__device__ float g_VT[(size_t)NZ * DHEAD * LL];   // V^T fp32 [z][e][kv]
__device__ float g_ctx[(size_t)BB * LL * (HH * DHEAD)];

// ===========================================================================
// tf32 mma.sync (m16n8k8) + bf16 mma.sync (m16n8k16) helpers
// ===========================================================================
__device__ __forceinline__ void mma_tf32(float* c,
                                         uint32_t a0, uint32_t a1, uint32_t a2, uint32_t a3,
                                         uint32_t b0, uint32_t b1)
{
    asm volatile(
        "mma.sync.aligned.m16n8k8.row.col.f32.tf32.tf32.f32 "
        "{%0,%1,%2,%3}, {%4,%5,%6,%7}, {%8,%9}, {%0,%1,%2,%3};"
        : "+f"(c[0]), "+f"(c[1]), "+f"(c[2]), "+f"(c[3])
        : "r"(a0), "r"(a1), "r"(a2), "r"(a3), "r"(b0), "r"(b1));
}
__device__ __forceinline__ uint32_t f2tf32(float x)
{
    uint32_t r;
    asm("cvt.rna.tf32.f32 %0, %1;" : "=r"(r) : "f"(x));
    return r;
}
__device__ __forceinline__ void mma_bf16(float* c,
                                         uint32_t a0, uint32_t a1, uint32_t a2, uint32_t a3,
                                         uint32_t b0, uint32_t b1)
{
    asm volatile(
        "mma.sync.aligned.m16n8k16.row.col.f32.bf16.bf16.f32 "
        "{%0,%1,%2,%3}, {%4,%5,%6,%7}, {%8,%9}, {%0,%1,%2,%3};"
        : "+f"(c[0]), "+f"(c[1]), "+f"(c[2]), "+f"(c[3])
        : "r"(a0), "r"(a1), "r"(a2), "r"(a3), "r"(b0), "r"(b1));
}
__device__ __forceinline__ void mma3(float* c,
                                     const uint32_t* ah, const uint32_t* al,
                                     const uint32_t* bh, const uint32_t* bl)
{
    mma_bf16(c, ah[0], ah[1], ah[2], ah[3], bh[0], bh[1]);
    mma_bf16(c, ah[0], ah[1], ah[2], ah[3], bl[0], bl[1]);
    mma_bf16(c, al[0], al[1], al[2], al[3], bh[0], bh[1]);
}
__device__ __forceinline__ void split_pair(float x, float y, uint32_t& h, uint32_t& l)
{
    __nv_bfloat16 hx = __float2bfloat16(x);
    __nv_bfloat16 hy = __float2bfloat16(y);
    __nv_bfloat162 hp = __halves2bfloat162(hx, hy);
    __nv_bfloat162 lp = __halves2bfloat162(__float2bfloat16(x - __bfloat162float(hx)),
                                           __float2bfloat16(y - __bfloat162float(hy)));
    h = *(uint32_t*)&hp;
    l = *(uint32_t*)&lp;
}
__device__ __forceinline__ void split_one(float x, __nv_bfloat16& h, __nv_bfloat16& l)
{
    h = __float2bfloat16(x);
    l = __float2bfloat16(x - __bfloat162float(h));
}
__device__ __forceinline__ uint4 cvt4(float4 v)
{
    uint4 r;
    r.x = f2tf32(v.x); r.y = f2tf32(v.y); r.z = f2tf32(v.z); r.w = f2tf32(v.w);
    return r;
}

// ===========================================================================
// score_mma: S[z,i,j] = 0.125 * Q·K^T   (tf32, natural layout, stride-72 rows,
// LDS.64 fragment loads via k-slot relabel: slot fc -> k=2fc, fc+4 -> 2fc+1)
// CTA 128x128, 512 threads / 16 warps (4x4), warp tile 32x32. 8 k8-steps.
// grid=(16 j, 16 i, 64 z), smem 73728 B
// ===========================================================================
__global__ __launch_bounds__(512) void score_mma(const float* __restrict__ Qp,
                                                 const float* __restrict__ Kp,
                                                 float* __restrict__ Sout)
{
    extern __shared__ char smraw[];
    uint32_t* Qs = (uint32_t*)smraw;        // [128][72]
    uint32_t* Ks = Qs + 128 * 72;           // [128][72]
    float* Ssm = (float*)smraw;             // epilogue reuse [128][132]

    const int tid = threadIdx.x, wid = tid >> 5, lane = tid & 31;
    const int wm = (wid >> 2) * 32, wn = (wid & 3) * 32;
    const int z = blockIdx.z, i0 = blockIdx.y * 128, j0 = blockIdx.x * 128;
    const float* Q = Qp + (size_t)z * LL * DHEAD;
    const float* K = Kp + (size_t)z * LL * DHEAD;

    #pragma unroll
    for (int t = 0; t < 4; t++) {
        int v = tid + t * 512;
        int r = v >> 4, c = (v & 15) * 4;
        *(uint4*)&Qs[r * 72 + c] = cvt4(*(const float4*)&Q[(size_t)(i0 + r) * DHEAD + c]);
        *(uint4*)&Ks[r * 72 + c] = cvt4(*(const float4*)&K[(size_t)(j0 + r) * DHEAD + c]);
    }
    __syncthreads();

    float acc[2][4][4] = {};
    const int fr = lane >> 2, fc = lane & 3;

    #pragma unroll
    for (int ks = 0; ks < 8; ks++) {
        const int k0 = ks * 8;
        uint2 bv[4];
        #pragma unroll
        for (int jn = 0; jn < 4; jn++) {
            int n = wn + jn * 8 + fr;
            bv[jn] = *(uint2*)&Ks[n * 72 + k0 + 2 * fc];   // k = k0+2fc, k0+2fc+1
        }
        #pragma unroll
        for (int im = 0; im < 2; im++) {
            int m = wm + im * 16 + fr;
            uint2 av0 = *(uint2*)&Qs[m * 72 + k0 + 2 * fc];
            uint2 av1 = *(uint2*)&Qs[(m + 8) * 72 + k0 + 2 * fc];
            #pragma unroll
            for (int jn = 0; jn < 4; jn++)
                mma_tf32(acc[im][jn], av0.x, av1.x, av0.y, av1.y, bv[jn].x, bv[jn].y);
        }
    }
    __syncthreads();

    const int qr = lane >> 2, qc = (lane & 3) * 2;
    #pragma unroll
    for (int im = 0; im < 2; im++) {
        int row = wm + im * 16 + qr;
        #pragma unroll
        for (int jn = 0; jn < 4; jn++) {
            int col = wn + jn * 8 + qc;
            *(float2*)&Ssm[row * 132 + col] =
                make_float2(acc[im][jn][0] * 0.125f, acc[im][jn][1] * 0.125f);
            *(float2*)&Ssm[(row + 8) * 132 + col] =
                make_float2(acc[im][jn][2] * 0.125f, acc[im][jn][3] * 0.125f);
        }
    }
    __syncthreads();

    float* S = Sout + (size_t)z * LL * LL;
    #pragma unroll
    for (int t = 0; t < 8; t++) {
        int v = tid + t * 512;
        int r = v >> 5, c = (v & 31) * 4;
        *(float4*)&S[(size_t)(i0 + r) * LL + j0 + c] = *(float4*)&Ssm[r * 132 + c];
    }
}

// ===========================================================================
// ctx_mma: C[z] = attn[z](2048x2048) @ V[z](2048x64)   (tf32, same scheme)
// CTA 128x64, 512 threads / 16 warps (8x2), warp tile 16x32. kv chunks of 64.
// grid=(16 i, 64 z), smem 55296 B
// ===========================================================================
__global__ __launch_bounds__(512) void ctx_mma(const float* __restrict__ Sm,
                                               const float* __restrict__ VT,
                                               float* __restrict__ Ctx)
{
    extern __shared__ char smraw[];
    uint32_t* As = (uint32_t*)smraw;        // [128][72]
    uint32_t* Ts = As + 128 * 72;           // V^T chunk [64][72]
    float* Cs = (float*)smraw;              // epilogue reuse [128][68]

    const int tid = threadIdx.x, wid = tid >> 5, lane = tid & 31;
    const int wm = (wid >> 1) * 16, wn = (wid & 1) * 32;
    const int z = blockIdx.y, b = z >> 4, h = z & 15;
    const int i0 = blockIdx.x * 128;
    const float* A = Sm + (size_t)z * LL * LL;

    const int fr = lane >> 2, fc = lane & 3;
    float acc[4][4] = {};

    for (int c = 0; c < 32; c++) {
        const int kv0 = c * 64;
        #pragma unroll
        for (int t = 0; t < 4; t++) {
            int v = tid + t * 512;
            int r = v >> 4, cc = (v & 15) * 4;
            *(uint4*)&As[r * 72 + cc] =
                cvt4(*(const float4*)&A[(size_t)(i0 + r) * LL + kv0 + cc]);
        }
        #pragma unroll
        for (int t = 0; t < 2; t++) {
            int v = tid + t * 512;
            int e = v >> 4, kp = (v & 15) * 4;
            *(uint4*)&Ts[e * 72 + kp] =
                cvt4(*(const float4*)&VT[((size_t)z * DHEAD + e) * LL + kv0 + kp]);
        }
        __syncthreads();

        #pragma unroll
        for (int ks = 0; ks < 8; ks++) {
            const int k0 = ks * 8;
            uint2 bv[4];
            #pragma unroll
            for (int jn = 0; jn < 4; jn++) {
                int n = wn + jn * 8 + fr;
                bv[jn] = *(uint2*)&Ts[n * 72 + k0 + 2 * fc];
            }
            int m = wm + fr;
            uint2 av0 = *(uint2*)&As[m * 72 + k0 + 2 * fc];
            uint2 av1 = *(uint2*)&As[(m + 8) * 72 + k0 + 2 * fc];
            #pragma unroll
            for (int jn = 0; jn < 4; jn++)
                mma_tf32(acc[jn], av0.x, av1.x, av0.y, av1.y, bv[jn].x, bv[jn].y);
        }
        __syncthreads();
    }

    const int qr = lane >> 2, qc = (lane & 3) * 2;
    {
        int row = wm + qr;
        #pragma unroll
        for (int jn = 0; jn < 4; jn++) {
            int col = wn + jn * 8 + qc;
            *(float2*)&Cs[row * 68 + col] = make_float2(acc[jn][0], acc[jn][1]);
            *(float2*)&Cs[(row + 8) * 68 + col] = make_float2(acc[jn][2], acc[jn][3]);
        }
    }
    __syncthreads();
    #pragma unroll
    for (int t = 0; t < 4; t++) {
        int v = tid + t * 512;
        int r = v >> 4, cc = (v & 15) * 4;
        *(float4*)&Ctx[((size_t)b * LL + i0 + r) * (HH * DHEAD) + h * DHEAD + cc] =
            *(float4*)&Cs[r * 68 + cc];
    }
}

// ===========================================================================
// proj_mma: Out[b,h,s,e] = sum_d X[b,s,d] W[h,d,e]   (split-bf16, R12-exact)
// mode 0: float row-major Q/K.  mode 1: V^T fp32 [z][e][kv].
// ===========================================================================
__global__ __launch_bounds__(256) void proj_mma(const float* __restrict__ X,
                                                const float* __restrict__ W,
                                                float* __restrict__ OutF,
                                                float* __restrict__ OutT,
                                                int mode)
{
    extern __shared__ char smraw[];
    __nv_bfloat16* XH = (__nv_bfloat16*)smraw;     // [128][40]
    __nv_bfloat16* XL = XH + 128 * 40;
    __nv_bfloat16* TH = XL + 128 * 40;             // W^T [64 e][40]
    __nv_bfloat16* TL = TH + 64 * 40;
    float* Cs = (float*)smraw;                     // [128][68]

    const int tid = threadIdx.x, wid = tid >> 5, lane = tid & 31;
    const int wm = (wid >> 1) * 32, wn = (wid & 1) * 32;
    const int b = blockIdx.z, hh = blockIdx.y, i0 = blockIdx.x * 128;
    const int z = b * HH + hh;
    const float* A  = X + (size_t)b * LL * DM;
    const float* Bw = W + (size_t)hh * DM * DHEAD;

    const int qr = lane >> 2, qc = (lane & 3) * 2;
    float acc[2][4][4] = {};

    for (int c = 0; c < 32; c++) {
        const int k0g = c * 32;
        #pragma unroll
        for (int t = 0; t < 4; t++) {
            int v = tid + t * 256;
            int r = v >> 3, cc = (v & 7) * 4;
            float4 xv = *(const float4*)&A[(size_t)(i0 + r) * DM + k0g + cc];
            uint32_t h0, l0, h1, l1;
            split_pair(xv.x, xv.y, h0, l0);
            split_pair(xv.z, xv.w, h1, l1);
            *(uint32_t*)&XH[r * 40 + cc] = h0; *(uint32_t*)&XH[r * 40 + cc + 2] = h1;
            *(uint32_t*)&XL[r * 40 + cc] = l0; *(uint32_t*)&XL[r * 40 + cc + 2] = l1;
        }
        #pragma unroll
        for (int t = 0; t < 2; t++) {
            int v = tid + t * 256;
            int r = v >> 4, cc = (v & 15) * 4;
            float4 wv = *(const float4*)&Bw[(size_t)(k0g + r) * DHEAD + cc];
            float vals[4] = {wv.x, wv.y, wv.z, wv.w};
            #pragma unroll
            for (int jj = 0; jj < 4; jj++) {
                __nv_bfloat16 hh2, ll;
                split_one(vals[jj], hh2, ll);
                TH[(cc + jj) * 40 + r] = hh2;
                TL[(cc + jj) * 40 + r] = ll;
            }
        }
        __syncthreads();

        #pragma unroll
        for (int ks = 0; ks < 2; ks++) {
            const int k0 = ks * 16;
            uint32_t bh[4][2], bl[4][2];
            #pragma unroll
            for (int jn = 0; jn < 4; jn++) {
                int n = wn + jn * 8 + qr;
                bh[jn][0] = *(uint32_t*)&TH[n * 40 + k0 + qc];
                bh[jn][1] = *(uint32_t*)&TH[n * 40 + k0 + 8 + qc];
                bl[jn][0] = *(uint32_t*)&TL[n * 40 + k0 + qc];
                bl[jn][1] = *(uint32_t*)&TL[n * 40 + k0 + 8 + qc];
            }
            #pragma unroll
            for (int im = 0; im < 2; im++) {
                int m = wm + im * 16 + qr;
                uint32_t ah[4], al[4];
                ah[0] = *(uint32_t*)&XH[m * 40 + k0 + qc];
                ah[1] = *(uint32_t*)&XH[(m + 8) * 40 + k0 + qc];
                ah[2] = *(uint32_t*)&XH[m * 40 + k0 + 8 + qc];
                ah[3] = *(uint32_t*)&XH[(m + 8) * 40 + k0 + 8 + qc];
                al[0] = *(uint32_t*)&XL[m * 40 + k0 + qc];
                al[1] = *(uint32_t*)&XL[(m + 8) * 40 + k0 + qc];
                al[2] = *(uint32_t*)&XL[m * 40 + k0 + 8 + qc];
                al[3] = *(uint32_t*)&XL[(m + 8) * 40 + k0 + 8 + qc];
                #pragma unroll
                for (int jn = 0; jn < 4; jn++)
                    mma3(acc[im][jn], ah, al, bh[jn], bl[jn]);
            }
        }
        __syncthreads();
    }

    #pragma unroll
    for (int im = 0; im < 2; im++) {
        int row = wm + im * 16 + qr;
        #pragma unroll
        for (int jn = 0; jn < 4; jn++) {
            int col = wn + jn * 8 + qc;
            *(float2*)&Cs[row * 68 + col] = make_float2(acc[im][jn][0], acc[im][jn][1]);
            *(float2*)&Cs[(row + 8) * 68 + col] = make_float2(acc[im][jn][2], acc[im][jn][3]);
        }
    }
    __syncthreads();

    if (mode == 0) {
        float* Out = OutF + ((size_t)z * LL + i0) * DHEAD;
        #pragma unroll
        for (int t = 0; t < 8; t++) {
            int v = tid + t * 256;
            int r = v >> 4, cc = (v & 15) * 4;
            *(float4*)&Out[(size_t)r * DHEAD + cc] = *(float4*)&Cs[r * 68 + cc];
        }
    } else {
        // V^T fp32: [z][e][kv]
        #pragma unroll
        for (int t = 0; t < 32; t++) {
            int v = tid + t * 256;
            int e = v >> 7, row = v & 127;
            OutT[((size_t)z * DHEAD + e) * LL + i0 + row] = Cs[row * 68 + e];
        }
    }
}

// ===========================================================================
// out_mma: Out(8192x1024) = Ctx(8192x1024) @ Wo(1024x1024)   (split-bf16)
// ===========================================================================
__global__ __launch_bounds__(256) void out_mma(const float* __restrict__ Ctx,
                                               const float* __restrict__ Wo,
                                               float* __restrict__ Out)
{
    extern __shared__ char smraw[];
    __nv_bfloat16* XH = (__nv_bfloat16*)smraw;     // [128][40]
    __nv_bfloat16* XL = XH + 128 * 40;
    __nv_bfloat16* TH = XL + 128 * 40;             // Wo^T [64 n][40]
    __nv_bfloat16* TL = TH + 64 * 40;
    float* Cs = (float*)smraw;

    const int tid = threadIdx.x, wid = tid >> 5, lane = tid & 31;
    const int wm = (wid >> 1) * 32, wn = (wid & 1) * 32;
    const int i0 = blockIdx.y * 128, j0 = blockIdx.x * 64;
    const int NN = HH * DHEAD;

    const int qr = lane >> 2, qc = (lane & 3) * 2;
    float acc[2][4][4] = {};

    for (int c = 0; c < 32; c++) {
        const int k0g = c * 32;
        #pragma unroll
        for (int t = 0; t < 4; t++) {
            int v = tid + t * 256;
            int r = v >> 3, cc = (v & 7) * 4;
            float4 xv = *(const float4*)&Ctx[(size_t)(i0 + r) * NN + k0g + cc];
            uint32_t h0, l0, h1, l1;
            split_pair(xv.x, xv.y, h0, l0);
            split_pair(xv.z, xv.w, h1, l1);
            *(uint32_t*)&XH[r * 40 + cc] = h0; *(uint32_t*)&XH[r * 40 + cc + 2] = h1;
            *(uint32_t*)&XL[r * 40 + cc] = l0; *(uint32_t*)&XL[r * 40 + cc + 2] = l1;
        }
        #pragma unroll
        for (int t = 0; t < 2; t++) {
            int v = tid + t * 256;
            int r = v >> 4, cc = (v & 15) * 4;
            float4 wv = *(const float4*)&Wo[(size_t)(k0g + r) * DM + j0 + cc];
            float vals[4] = {wv.x, wv.y, wv.z, wv.w};
            #pragma unroll
            for (int jj = 0; jj < 4; jj++) {
                __nv_bfloat16 hh, ll;
                split_one(vals[jj], hh, ll);
                TH[(cc + jj) * 40 + r] = hh;
                TL[(cc + jj) * 40 + r] = ll;
            }
        }
        __syncthreads();

        #pragma unroll
        for (int ks = 0; ks < 2; ks++) {
            const int k0 = ks * 16;
            uint32_t bh[4][2], bl[4][2];
            #pragma unroll
            for (int jn = 0; jn < 4; jn++) {
                int n = wn + jn * 8 + qr;
                bh[jn][0] = *(uint32_t*)&TH[n * 40 + k0 + qc];
                bh[jn][1] = *(uint32_t*)&TH[n * 40 + k0 + 8 + qc];
                bl[jn][0] = *(uint32_t*)&TL[n * 40 + k0 + qc];
                bl[jn][1] = *(uint32_t*)&TL[n * 40 + k0 + 8 + qc];
            }
            #pragma unroll
            for (int im = 0; im < 2; im++) {
                int m = wm + im * 16 + qr;
                uint32_t ah[4], al[4];
                ah[0] = *(uint32_t*)&XH[m * 40 + k0 + qc];
                ah[1] = *(uint32_t*)&XH[(m + 8) * 40 + k0 + qc];
                ah[2] = *(uint32_t*)&XH[m * 40 + k0 + 8 + qc];
                ah[3] = *(uint32_t*)&XH[(m + 8) * 40 + k0 + 8 + qc];
                al[0] = *(uint32_t*)&XL[m * 40 + k0 + qc];
                al[1] = *(uint32_t*)&XL[(m + 8) * 40 + k0 + qc];
                al[2] = *(uint32_t*)&XL[m * 40 + k0 + 8 + qc];
                al[3] = *(uint32_t*)&XL[(m + 8) * 40 + k0 + 8 + qc];
                #pragma unroll
                for (int jn = 0; jn < 4; jn++)
                    mma3(acc[im][jn], ah, al, bh[jn], bl[jn]);
            }
        }
        __syncthreads();
    }

    #pragma unroll
    for (int im = 0; im < 2; im++) {
        int row = wm + im * 16 + qr;
        #pragma unroll
        for (int jn = 0; jn < 4; jn++) {
            int col = wn + jn * 8 + qc;
            *(float2*)&Cs[row * 68 + col] = make_float2(acc[im][jn][0], acc[im][jn][1]);
            *(float2*)&Cs[(row + 8) * 68 + col] = make_float2(acc[im][jn][2], acc[im][jn][3]);
        }
    }
    __syncthreads();
    #pragma unroll
    for (int t = 0; t < 8; t++) {
        int v = tid + t * 256;
        int r = v >> 4, cc = (v & 15) * 4;
        *(float4*)&Out[(size_t)(i0 + r) * DM + j0 + cc] = *(float4*)&Cs[r * 68 + cc];
    }
}

// ===========================================================================
// Row softmax, 2048 elems, in place. grid=(131072), block=256
// ===========================================================================
__global__ __launch_bounds__(256) void softmax_kernel(float* __restrict__ S)
{
    float4* p4 = (float4*)(S + (size_t)blockIdx.x * LL);
    const int tid = threadIdx.x;
    const int warp = tid >> 5, lane = tid & 31;
    __shared__ float red[8];

    float4 v0 = p4[tid], v1 = p4[tid + 256];
    float m = fmaxf(fmaxf(fmaxf(v0.x, v0.y), fmaxf(v0.z, v0.w)),
                    fmaxf(fmaxf(v1.x, v1.y), fmaxf(v1.z, v1.w)));
    #pragma unroll
    for (int o = 16; o > 0; o >>= 1) m = fmaxf(m, __shfl_xor_sync(0xffffffffu, m, o));
    if (lane == 0) red[warp] = m;
    __syncthreads();
    if (tid < 8) {
        float t = red[tid];
        #pragma unroll
        for (int o = 4; o > 0; o >>= 1) t = fmaxf(t, __shfl_xor_sync(0xffu, t, o));
        if (tid == 0) red[0] = t;
    }
    __syncthreads();
    m = red[0];
    __syncthreads();

    v0.x = __expf(v0.x - m); v0.y = __expf(v0.y - m);
    v0.z = __expf(v0.z - m); v0.w = __expf(v0.w - m);
    v1.x = __expf(v1.x - m); v1.y = __expf(v1.y - m);
    v1.z = __expf(v1.z - m); v1.w = __expf(v1.w - m);
    float s = v0.x + v0.y + v0.z + v0.w + v1.x + v1.y + v1.z + v1.w;
    #pragma unroll
    for (int o = 16; o > 0; o >>= 1) s += __shfl_xor_sync(0xffffffffu, s, o);
    if (lane == 0) red[warp] = s;
    __syncthreads();
    if (tid < 8) {
        float t = red[tid];
        #pragma unroll
        for (int o = 4; o > 0; o >>= 1) t += __shfl_xor_sync(0xffu, t, o);
        if (tid == 0) red[0] = t;
    }
    __syncthreads();
    float inv = 1.0f / red[0];

    v0.x *= inv; v0.y *= inv; v0.z *= inv; v0.w *= inv;
    v1.x *= inv; v1.y *= inv; v1.z *= inv; v1.w *= inv;
    p4[tid] = v0; p4[tid + 256] = v1;
}

// ===========================================================================
extern "C" void kernel_launch(void* const* d_in, const int* in_sizes, int n_in,
                              void* d_out, int out_size)
{
    const float* q  = (const float*)d_in[0];
    const float* k  = (const float*)d_in[1];
    const float* v  = (const float*)d_in[2];
    const float* wq = (const float*)d_in[3];
    const float* wk = (const float*)d_in[4];
    const float* wv = (const float*)d_in[5];
    const float* wo = (const float*)d_in[6];

    float* out = (float*)d_out;
    const size_t OUT_ELEMS = (size_t)BB * LL * DM;

    float *gQ, *gK, *gVT, *gCtx;
    cudaGetSymbolAddress((void**)&gQ, g_Q);
    cudaGetSymbolAddress((void**)&gK, g_K);
    cudaGetSymbolAddress((void**)&gVT, g_VT);
    cudaGetSymbolAddress((void**)&gCtx, g_ctx);

    float* attn = out + OUT_ELEMS;

    const int proj_smem = 34816;
    cudaFuncSetAttribute(proj_mma, cudaFuncAttributeMaxDynamicSharedMemorySize, proj_smem);
    proj_mma<<<dim3(LL / 128, HH, BB), dim3(256), proj_smem>>>(q, wq, gQ, nullptr, 0);
    proj_mma<<<dim3(LL / 128, HH, BB), dim3(256), proj_smem>>>(k, wk, gK, nullptr, 0);
    proj_mma<<<dim3(LL / 128, HH, BB), dim3(256), proj_smem>>>(v, wv, nullptr, gVT, 1);

    const int score_smem = 73728;
    cudaFuncSetAttribute(score_mma, cudaFuncAttributeMaxDynamicSharedMemorySize, score_smem);
    score_mma<<<dim3(LL / 128, LL / 128, NZ), dim3(512), score_smem>>>(gQ, gK, attn);

    softmax_kernel<<<dim3(NZ * LL), dim3(256)>>>(attn);

    const int ctx_smem = 55296;
    cudaFuncSetAttribute(ctx_mma, cudaFuncAttributeMaxDynamicSharedMemorySize, ctx_smem);
    ctx_mma<<<dim3(LL / 128, NZ), dim3(512), ctx_smem>>>(attn, gVT, gCtx);

    const int out_smem = 34816;
    cudaFuncSetAttribute(out_mma, cudaFuncAttributeMaxDynamicSharedMemorySize, out_smem);
    out_mma<<<dim3(DM / 64, (BB * LL) / 128), dim3(256), out_smem>>>(gCtx, wo, out);
}

// round 17
// speedup vs baseline: 1.3193x; 1.1770x over previous
#include <cuda_runtime.h>
#include <cuda_bf16.h>
#include <cstdint>

#define BB 4
#define HH 16
#define LL 2048
#define DM 1024
#define DHEAD 64
#define NZ (BB * HH)

// Scratch (__device__ globals; allocation-free rule)
__device__ float g_Q[(size_t)NZ * LL * DHEAD];
__device__ float g_K[(size_t)NZ * LL * DHEAD];
__device__ float g_VT[(size_t)NZ * DHEAD * LL];   // V^T fp32 [z][e][kv]
__device__ float g_ctx[(size_t)BB * LL * (HH * DHEAD)];
__device__ __nv_bfloat16 g_XH[(size_t)BB * LL * DM];   // input / ctx hi plane (reused)
__device__ __nv_bfloat16 g_XL[(size_t)BB * LL * DM];   // input / ctx lo plane
__device__ __nv_bfloat16 g_WTH[(size_t)DM * DM];       // weight^T hi plane (reused)
__device__ __nv_bfloat16 g_WTL[(size_t)DM * DM];       // weight^T lo plane

// ===========================================================================
// mma helpers
// ===========================================================================
__device__ __forceinline__ void mma_tf32(float* c,
                                         uint32_t a0, uint32_t a1, uint32_t a2, uint32_t a3,
                                         uint32_t b0, uint32_t b1)
{
    asm volatile(
        "mma.sync.aligned.m16n8k8.row.col.f32.tf32.tf32.f32 "
        "{%0,%1,%2,%3}, {%4,%5,%6,%7}, {%8,%9}, {%0,%1,%2,%3};"
        : "+f"(c[0]), "+f"(c[1]), "+f"(c[2]), "+f"(c[3])
        : "r"(a0), "r"(a1), "r"(a2), "r"(a3), "r"(b0), "r"(b1));
}
__device__ __forceinline__ uint32_t f2tf32(float x)
{
    uint32_t r;
    asm("cvt.rna.tf32.f32 %0, %1;" : "=r"(r) : "f"(x));
    return r;
}
__device__ __forceinline__ void mma_bf16(float* c,
                                         uint32_t a0, uint32_t a1, uint32_t a2, uint32_t a3,
                                         uint32_t b0, uint32_t b1)
{
    asm volatile(
        "mma.sync.aligned.m16n8k16.row.col.f32.bf16.bf16.f32 "
        "{%0,%1,%2,%3}, {%4,%5,%6,%7}, {%8,%9}, {%0,%1,%2,%3};"
        : "+f"(c[0]), "+f"(c[1]), "+f"(c[2]), "+f"(c[3])
        : "r"(a0), "r"(a1), "r"(a2), "r"(a3), "r"(b0), "r"(b1));
}
__device__ __forceinline__ void mma3(float* c,
                                     const uint32_t* ah, const uint32_t* al,
                                     const uint32_t* bh, const uint32_t* bl)
{
    mma_bf16(c, ah[0], ah[1], ah[2], ah[3], bh[0], bh[1]);
    mma_bf16(c, ah[0], ah[1], ah[2], ah[3], bl[0], bl[1]);
    mma_bf16(c, al[0], al[1], al[2], al[3], bh[0], bh[1]);
}
__device__ __forceinline__ void split_pair(float x, float y, uint32_t& h, uint32_t& l)
{
    __nv_bfloat16 hx = __float2bfloat16(x);
    __nv_bfloat16 hy = __float2bfloat16(y);
    __nv_bfloat162 hp = __halves2bfloat162(hx, hy);
    __nv_bfloat162 lp = __halves2bfloat162(__float2bfloat16(x - __bfloat162float(hx)),
                                           __float2bfloat16(y - __bfloat162float(hy)));
    h = *(uint32_t*)&hp;
    l = *(uint32_t*)&lp;
}
__device__ __forceinline__ void split_one(float x, __nv_bfloat16& h, __nv_bfloat16& l)
{
    h = __float2bfloat16(x);
    l = __float2bfloat16(x - __bfloat162float(h));
}

// ===========================================================================
// presplit: fp32 -> bf16 hi/lo planes (grid-stride, vectorized)
// ===========================================================================
__global__ __launch_bounds__(256) void presplit(const float4* __restrict__ src,
                                                uint2* __restrict__ dH,
                                                uint2* __restrict__ dL, int n4)
{
    int i = blockIdx.x * 256 + threadIdx.x;
    int stride = gridDim.x * 256;
    for (; i < n4; i += stride) {
        float4 v = src[i];
        uint32_t h0, l0, h1, l1;
        split_pair(v.x, v.y, h0, l0);
        split_pair(v.z, v.w, h1, l1);
        dH[i] = make_uint2(h0, h1);
        dL[i] = make_uint2(l0, l1);
    }
}

// ===========================================================================
// transsplit: src (batch, R, C) fp32 -> dH/dL (batch, C, R) bf16 planes
// block 256, grid (C/32, R/32, batch)
// ===========================================================================
__global__ __launch_bounds__(256) void transsplit(const float* __restrict__ src,
                                                  __nv_bfloat16* __restrict__ dH,
                                                  __nv_bfloat16* __restrict__ dL,
                                                  int R, int C)
{
    __shared__ float tile[32][33];
    const int bz = blockIdx.z;
    const int c0 = blockIdx.x * 32, r0 = blockIdx.y * 32;
    const float* s = src + (size_t)bz * R * C;
    __nv_bfloat16* oH = dH + (size_t)bz * R * C;
    __nv_bfloat16* oL = dL + (size_t)bz * R * C;
    const int tx = threadIdx.x & 31, ty = threadIdx.x >> 5;
    #pragma unroll
    for (int i = 0; i < 32; i += 8)
        tile[ty + i][tx] = s[(size_t)(r0 + ty + i) * C + c0 + tx];
    __syncthreads();
    #pragma unroll
    for (int i = 0; i < 32; i += 8) {
        float v = tile[tx][ty + i];
        __nv_bfloat16 h, l;
        split_one(v, h, l);
        size_t o = (size_t)(c0 + ty + i) * R + r0 + tx;
        oH[o] = h;
        oL[o] = l;
    }
}

// ===========================================================================
// score_mma: S[z,i,j] = 0.125 * Q·K^T   (tf32, R12-exact)
// CTA 128x128, 512 threads / 16 warps (4x4), warp tile 32x32. 8 k8-steps.
// grid=(16 j, 16 i, 64 z), smem 69632 B
// ===========================================================================
__global__ __launch_bounds__(512) void score_mma(const float* __restrict__ Qp,
                                                 const float* __restrict__ Kp,
                                                 float* __restrict__ Sout)
{
    extern __shared__ char smraw[];
    uint32_t* Qs = (uint32_t*)smraw;        // [128][68]
    uint32_t* Ks = Qs + 128 * 68;           // [128][68]
    float* Ssm = (float*)smraw;             // epilogue reuse [128][132]

    const int tid = threadIdx.x, wid = tid >> 5, lane = tid & 31;
    const int wm = (wid >> 2) * 32, wn = (wid & 3) * 32;
    const int z = blockIdx.z, i0 = blockIdx.y * 128, j0 = blockIdx.x * 128;
    const float* Q = Qp + (size_t)z * LL * DHEAD;
    const float* K = Kp + (size_t)z * LL * DHEAD;

    #pragma unroll
    for (int t = 0; t < 4; t++) {
        int v = tid + t * 512;
        int r = v >> 4, c = (v & 15) * 4;
        float4 qv = *(const float4*)&Q[(size_t)(i0 + r) * DHEAD + c];
        Qs[r * 68 + c + 0] = f2tf32(qv.x); Qs[r * 68 + c + 1] = f2tf32(qv.y);
        Qs[r * 68 + c + 2] = f2tf32(qv.z); Qs[r * 68 + c + 3] = f2tf32(qv.w);
        float4 kv = *(const float4*)&K[(size_t)(j0 + r) * DHEAD + c];
        Ks[r * 68 + c + 0] = f2tf32(kv.x); Ks[r * 68 + c + 1] = f2tf32(kv.y);
        Ks[r * 68 + c + 2] = f2tf32(kv.z); Ks[r * 68 + c + 3] = f2tf32(kv.w);
    }
    __syncthreads();

    float acc[2][4][4] = {};
    const int fr = lane >> 2, fc = lane & 3;

    #pragma unroll
    for (int ks = 0; ks < 8; ks++) {
        const int k0 = ks * 8;
        uint32_t b0[4], b1[4];
        #pragma unroll
        for (int jn = 0; jn < 4; jn++) {
            int n = wn + jn * 8 + fr;
            b0[jn] = Ks[n * 68 + k0 + fc];
            b1[jn] = Ks[n * 68 + k0 + fc + 4];
        }
        #pragma unroll
        for (int im = 0; im < 2; im++) {
            int m = wm + im * 16 + fr;
            uint32_t a0 = Qs[m * 68 + k0 + fc];
            uint32_t a1 = Qs[(m + 8) * 68 + k0 + fc];
            uint32_t a2 = Qs[m * 68 + k0 + fc + 4];
            uint32_t a3 = Qs[(m + 8) * 68 + k0 + fc + 4];
            #pragma unroll
            for (int jn = 0; jn < 4; jn++)
                mma_tf32(acc[im][jn], a0, a1, a2, a3, b0[jn], b1[jn]);
        }
    }
    __syncthreads();

    const int qr = lane >> 2, qc = (lane & 3) * 2;
    #pragma unroll
    for (int im = 0; im < 2; im++) {
        int row = wm + im * 16 + qr;
        #pragma unroll
        for (int jn = 0; jn < 4; jn++) {
            int col = wn + jn * 8 + qc;
            *(float2*)&Ssm[row * 132 + col] =
                make_float2(acc[im][jn][0] * 0.125f, acc[im][jn][1] * 0.125f);
            *(float2*)&Ssm[(row + 8) * 132 + col] =
                make_float2(acc[im][jn][2] * 0.125f, acc[im][jn][3] * 0.125f);
        }
    }
    __syncthreads();

    float* S = Sout + (size_t)z * LL * LL;
    #pragma unroll
    for (int t = 0; t < 8; t++) {
        int v = tid + t * 512;
        int r = v >> 5, c = (v & 31) * 4;
        *(float4*)&S[(size_t)(i0 + r) * LL + j0 + c] = *(float4*)&Ssm[r * 132 + c];
    }
}

// ===========================================================================
// ctx_mma: C[z] = attn[z] @ V[z]   (tf32, R12-exact)
// CTA 128x64, 512 threads / 16 warps (8x2), warp tile 16x32. kv chunks of 64.
// grid=(16 i, 64 z), smem 52224 B
// ===========================================================================
__global__ __launch_bounds__(512) void ctx_mma(const float* __restrict__ Sm,
                                               const float* __restrict__ VT,
                                               float* __restrict__ Ctx)
{
    extern __shared__ char smraw[];
    uint32_t* As = (uint32_t*)smraw;        // [128][68]
    uint32_t* Ts = As + 128 * 68;           // V^T chunk [64][68]
    float* Cs = (float*)smraw;              // epilogue reuse [128][68]

    const int tid = threadIdx.x, wid = tid >> 5, lane = tid & 31;
    const int wm = (wid >> 1) * 16, wn = (wid & 1) * 32;
    const int z = blockIdx.y, b = z >> 4, h = z & 15;
    const int i0 = blockIdx.x * 128;
    const float* A = Sm + (size_t)z * LL * LL;

    const int fr = lane >> 2, fc = lane & 3;
    float acc[4][4] = {};

    for (int c = 0; c < 32; c++) {
        const int kv0 = c * 64;
        #pragma unroll
        for (int t = 0; t < 4; t++) {
            int v = tid + t * 512;
            int r = v >> 4, cc = (v & 15) * 4;
            float4 av = *(const float4*)&A[(size_t)(i0 + r) * LL + kv0 + cc];
            As[r * 68 + cc + 0] = f2tf32(av.x); As[r * 68 + cc + 1] = f2tf32(av.y);
            As[r * 68 + cc + 2] = f2tf32(av.z); As[r * 68 + cc + 3] = f2tf32(av.w);
        }
        #pragma unroll
        for (int t = 0; t < 2; t++) {
            int v = tid + t * 512;
            int e = v >> 4, kp = (v & 15) * 4;
            float4 vv = *(const float4*)&VT[((size_t)z * DHEAD + e) * LL + kv0 + kp];
            Ts[e * 68 + kp + 0] = f2tf32(vv.x); Ts[e * 68 + kp + 1] = f2tf32(vv.y);
            Ts[e * 68 + kp + 2] = f2tf32(vv.z); Ts[e * 68 + kp + 3] = f2tf32(vv.w);
        }
        __syncthreads();

        #pragma unroll
        for (int ks = 0; ks < 8; ks++) {
            const int k0 = ks * 8;
            uint32_t b0[4], b1[4];
            #pragma unroll
            for (int jn = 0; jn < 4; jn++) {
                int n = wn + jn * 8 + fr;
                b0[jn] = Ts[n * 68 + k0 + fc];
                b1[jn] = Ts[n * 68 + k0 + fc + 4];
            }
            int m = wm + fr;
            uint32_t a0 = As[m * 68 + k0 + fc];
            uint32_t a1 = As[(m + 8) * 68 + k0 + fc];
            uint32_t a2 = As[m * 68 + k0 + fc + 4];
            uint32_t a3 = As[(m + 8) * 68 + k0 + fc + 4];
            #pragma unroll
            for (int jn = 0; jn < 4; jn++)
                mma_tf32(acc[jn], a0, a1, a2, a3, b0[jn], b1[jn]);
        }
        __syncthreads();
    }

    const int qr = lane >> 2, qc = (lane & 3) * 2;
    {
        int row = wm + qr;
        #pragma unroll
        for (int jn = 0; jn < 4; jn++) {
            int col = wn + jn * 8 + qc;
            *(float2*)&Cs[row * 68 + col] = make_float2(acc[jn][0], acc[jn][1]);
            *(float2*)&Cs[(row + 8) * 68 + col] = make_float2(acc[jn][2], acc[jn][3]);
        }
    }
    __syncthreads();
    #pragma unroll
    for (int t = 0; t < 4; t++) {
        int v = tid + t * 512;
        int r = v >> 4, cc = (v & 15) * 4;
        *(float4*)&Ctx[((size_t)b * LL + i0 + r) * (HH * DHEAD) + h * DHEAD + cc] =
            *(float4*)&Cs[r * 68 + cc];
    }
}

// ===========================================================================
// proj_v2: Out[b,h,s,e] = sum_d X[b,s,d] W[h,d,e]  (split-bf16 MMA, pre-split
// planes: XH/XL [b][s][d], WTH/WTL [h][e][d]). Mainloop = R12-exact.
// mode 0: float row-major Q/K.  mode 1: V^T fp32 [z][e][kv].
// grid=(16, 16, 4), block 256, smem 34816 B
// ===========================================================================
__global__ __launch_bounds__(256) void proj_v2(const __nv_bfloat16* __restrict__ XHp,
                                               const __nv_bfloat16* __restrict__ XLp,
                                               const __nv_bfloat16* __restrict__ WTHp,
                                               const __nv_bfloat16* __restrict__ WTLp,
                                               float* __restrict__ OutF,
                                               float* __restrict__ OutT,
                                               int mode)
{
    extern __shared__ char smraw[];
    __nv_bfloat16* XH = (__nv_bfloat16*)smraw;     // [128][40]
    __nv_bfloat16* XL = XH + 128 * 40;
    __nv_bfloat16* TH = XL + 128 * 40;             // W^T [64 e][40]
    __nv_bfloat16* TL = TH + 64 * 40;
    float* Cs = (float*)smraw;                     // [128][68]

    const int tid = threadIdx.x, wid = tid >> 5, lane = tid & 31;
    const int wm = (wid >> 1) * 32, wn = (wid & 1) * 32;
    const int b = blockIdx.z, hh = blockIdx.y, i0 = blockIdx.x * 128;
    const int z = b * HH + hh;
    const __nv_bfloat16* Xh = XHp + (size_t)b * LL * DM;
    const __nv_bfloat16* Xl = XLp + (size_t)b * LL * DM;
    const __nv_bfloat16* Wh = WTHp + (size_t)hh * DHEAD * DM;
    const __nv_bfloat16* Wl = WTLp + (size_t)hh * DHEAD * DM;

    const int qr = lane >> 2, qc = (lane & 3) * 2;
    float acc[2][4][4] = {};

    for (int c = 0; c < 32; c++) {
        const int k0g = c * 32;
        // A tile 128x32: vectorized plane copies
        #pragma unroll
        for (int t = 0; t < 2; t++) {
            int v = tid + t * 256;
            int r = v >> 2, cc = (v & 3) * 8;
            *(uint4*)&XH[r * 40 + cc] = *(const uint4*)&Xh[(size_t)(i0 + r) * DM + k0g + cc];
            *(uint4*)&XL[r * 40 + cc] = *(const uint4*)&Xl[(size_t)(i0 + r) * DM + k0g + cc];
        }
        // B tile 64x32 (already transposed in gmem)
        {
            int e = tid >> 2, cc = (tid & 3) * 8;
            *(uint4*)&TH[e * 40 + cc] = *(const uint4*)&Wh[(size_t)e * DM + k0g + cc];
            *(uint4*)&TL[e * 40 + cc] = *(const uint4*)&Wl[(size_t)e * DM + k0g + cc];
        }
        __syncthreads();

        #pragma unroll
        for (int ks = 0; ks < 2; ks++) {
            const int k0 = ks * 16;
            uint32_t bh[4][2], bl[4][2];
            #pragma unroll
            for (int jn = 0; jn < 4; jn++) {
                int n = wn + jn * 8 + qr;
                bh[jn][0] = *(uint32_t*)&TH[n * 40 + k0 + qc];
                bh[jn][1] = *(uint32_t*)&TH[n * 40 + k0 + 8 + qc];
                bl[jn][0] = *(uint32_t*)&TL[n * 40 + k0 + qc];
                bl[jn][1] = *(uint32_t*)&TL[n * 40 + k0 + 8 + qc];
            }
            #pragma unroll
            for (int im = 0; im < 2; im++) {
                int m = wm + im * 16 + qr;
                uint32_t ah[4], al[4];
                ah[0] = *(uint32_t*)&XH[m * 40 + k0 + qc];
                ah[1] = *(uint32_t*)&XH[(m + 8) * 40 + k0 + qc];
                ah[2] = *(uint32_t*)&XH[m * 40 + k0 + 8 + qc];
                ah[3] = *(uint32_t*)&XH[(m + 8) * 40 + k0 + 8 + qc];
                al[0] = *(uint32_t*)&XL[m * 40 + k0 + qc];
                al[1] = *(uint32_t*)&XL[(m + 8) * 40 + k0 + qc];
                al[2] = *(uint32_t*)&XL[m * 40 + k0 + 8 + qc];
                al[3] = *(uint32_t*)&XL[(m + 8) * 40 + k0 + 8 + qc];
                #pragma unroll
                for (int jn = 0; jn < 4; jn++)
                    mma3(acc[im][jn], ah, al, bh[jn], bl[jn]);
            }
        }
        __syncthreads();
    }

    #pragma unroll
    for (int im = 0; im < 2; im++) {
        int row = wm + im * 16 + qr;
        #pragma unroll
        for (int jn = 0; jn < 4; jn++) {
            int col = wn + jn * 8 + qc;
            *(float2*)&Cs[row * 68 + col] = make_float2(acc[im][jn][0], acc[im][jn][1]);
            *(float2*)&Cs[(row + 8) * 68 + col] = make_float2(acc[im][jn][2], acc[im][jn][3]);
        }
    }
    __syncthreads();

    if (mode == 0) {
        float* Out = OutF + ((size_t)z * LL + i0) * DHEAD;
        #pragma unroll
        for (int t = 0; t < 8; t++) {
            int v = tid + t * 256;
            int r = v >> 4, cc = (v & 15) * 4;
            *(float4*)&Out[(size_t)r * DHEAD + cc] = *(float4*)&Cs[r * 68 + cc];
        }
    } else {
        // V^T fp32: [z][e][kv]
        #pragma unroll
        for (int t = 0; t < 32; t++) {
            int v = tid + t * 256;
            int e = v >> 7, row = v & 127;
            OutT[((size_t)z * DHEAD + e) * LL + i0 + row] = Cs[row * 68 + e];
        }
    }
}

// ===========================================================================
// out_v2: Out(8192x1024) = Ctx @ Wo  (split-bf16 MMA, pre-split planes:
// CtxH/L [row][1024], WoT H/L [n][k]). Mainloop = R12-exact.
// grid=(16 j, 64 i), block 256, smem 34816 B
// ===========================================================================
__global__ __launch_bounds__(256) void out_v2(const __nv_bfloat16* __restrict__ CHp,
                                              const __nv_bfloat16* __restrict__ CLp,
                                              const __nv_bfloat16* __restrict__ WTHp,
                                              const __nv_bfloat16* __restrict__ WTLp,
                                              float* __restrict__ Out)
{
    extern __shared__ char smraw[];
    __nv_bfloat16* XH = (__nv_bfloat16*)smraw;     // [128][40]
    __nv_bfloat16* XL = XH + 128 * 40;
    __nv_bfloat16* TH = XL + 128 * 40;             // WoT [64 n][40]
    __nv_bfloat16* TL = TH + 64 * 40;
    float* Cs = (float*)smraw;

    const int tid = threadIdx.x, wid = tid >> 5, lane = tid & 31;
    const int wm = (wid >> 1) * 32, wn = (wid & 1) * 32;
    const int i0 = blockIdx.y * 128, j0 = blockIdx.x * 64;
    const int NN = HH * DHEAD;

    const int qr = lane >> 2, qc = (lane & 3) * 2;
    float acc[2][4][4] = {};

    for (int c = 0; c < 32; c++) {
        const int k0g = c * 32;
        #pragma unroll
        for (int t = 0; t < 2; t++) {
            int v = tid + t * 256;
            int r = v >> 2, cc = (v & 3) * 8;
            *(uint4*)&XH[r * 40 + cc] = *(const uint4*)&CHp[(size_t)(i0 + r) * NN + k0g + cc];
            *(uint4*)&XL[r * 40 + cc] = *(const uint4*)&CLp[(size_t)(i0 + r) * NN + k0g + cc];
        }
        {
            int n = tid >> 2, cc = (tid & 3) * 8;
            *(uint4*)&TH[n * 40 + cc] = *(const uint4*)&WTHp[(size_t)(j0 + n) * DM + k0g + cc];
            *(uint4*)&TL[n * 40 + cc] = *(const uint4*)&WTLp[(size_t)(j0 + n) * DM + k0g + cc];
        }
        __syncthreads();

        #pragma unroll
        for (int ks = 0; ks < 2; ks++) {
            const int k0 = ks * 16;
            uint32_t bh[4][2], bl[4][2];
            #pragma unroll
            for (int jn = 0; jn < 4; jn++) {
                int n = wn + jn * 8 + qr;
                bh[jn][0] = *(uint32_t*)&TH[n * 40 + k0 + qc];
                bh[jn][1] = *(uint32_t*)&TH[n * 40 + k0 + 8 + qc];
                bl[jn][0] = *(uint32_t*)&TL[n * 40 + k0 + qc];
                bl[jn][1] = *(uint32_t*)&TL[n * 40 + k0 + 8 + qc];
            }
            #pragma unroll
            for (int im = 0; im < 2; im++) {
                int m = wm + im * 16 + qr;
                uint32_t ah[4], al[4];
                ah[0] = *(uint32_t*)&XH[m * 40 + k0 + qc];
                ah[1] = *(uint32_t*)&XH[(m + 8) * 40 + k0 + qc];
                ah[2] = *(uint32_t*)&XH[m * 40 + k0 + 8 + qc];
                ah[3] = *(uint32_t*)&XH[(m + 8) * 40 + k0 + 8 + qc];
                al[0] = *(uint32_t*)&XL[m * 40 + k0 + qc];
                al[1] = *(uint32_t*)&XL[(m + 8) * 40 + k0 + qc];
                al[2] = *(uint32_t*)&XL[m * 40 + k0 + 8 + qc];
                al[3] = *(uint32_t*)&XL[(m + 8) * 40 + k0 + 8 + qc];
                #pragma unroll
                for (int jn = 0; jn < 4; jn++)
                    mma3(acc[im][jn], ah, al, bh[jn], bl[jn]);
            }
        }
        __syncthreads();
    }

    #pragma unroll
    for (int im = 0; im < 2; im++) {
        int row = wm + im * 16 + qr;
        #pragma unroll
        for (int jn = 0; jn < 4; jn++) {
            int col = wn + jn * 8 + qc;
            *(float2*)&Cs[row * 68 + col] = make_float2(acc[im][jn][0], acc[im][jn][1]);
            *(float2*)&Cs[(row + 8) * 68 + col] = make_float2(acc[im][jn][2], acc[im][jn][3]);
        }
    }
    __syncthreads();
    #pragma unroll
    for (int t = 0; t < 8; t++) {
        int v = tid + t * 256;
        int r = v >> 4, cc = (v & 15) * 4;
        *(float4*)&Out[(size_t)(i0 + r) * DM + j0 + cc] = *(float4*)&Cs[r * 68 + cc];
    }
}

// ===========================================================================
// Row softmax, 2048 elems, in place. grid=(131072), block=256  (R12-exact)
// ===========================================================================
__global__ __launch_bounds__(256) void softmax_kernel(float* __restrict__ S)
{
    float4* p4 = (float4*)(S + (size_t)blockIdx.x * LL);
    const int tid = threadIdx.x;
    const int warp = tid >> 5, lane = tid & 31;
    __shared__ float red[8];

    float4 v0 = p4[tid], v1 = p4[tid + 256];
    float m = fmaxf(fmaxf(fmaxf(v0.x, v0.y), fmaxf(v0.z, v0.w)),
                    fmaxf(fmaxf(v1.x, v1.y), fmaxf(v1.z, v1.w)));
    #pragma unroll
    for (int o = 16; o > 0; o >>= 1) m = fmaxf(m, __shfl_xor_sync(0xffffffffu, m, o));
    if (lane == 0) red[warp] = m;
    __syncthreads();
    if (tid < 8) {
        float t = red[tid];
        #pragma unroll
        for (int o = 4; o > 0; o >>= 1) t = fmaxf(t, __shfl_xor_sync(0xffu, t, o));
        if (tid == 0) red[0] = t;
    }
    __syncthreads();
    m = red[0];
    __syncthreads();

    v0.x = __expf(v0.x - m); v0.y = __expf(v0.y - m);
    v0.z = __expf(v0.z - m); v0.w = __expf(v0.w - m);
    v1.x = __expf(v1.x - m); v1.y = __expf(v1.y - m);
    v1.z = __expf(v1.z - m); v1.w = __expf(v1.w - m);
    float s = v0.x + v0.y + v0.z + v0.w + v1.x + v1.y + v1.z + v1.w;
    #pragma unroll
    for (int o = 16; o > 0; o >>= 1) s += __shfl_xor_sync(0xffffffffu, s, o);
    if (lane == 0) red[warp] = s;
    __syncthreads();
    if (tid < 8) {
        float t = red[tid];
        #pragma unroll
        for (int o = 4; o > 0; o >>= 1) t += __shfl_xor_sync(0xffu, t, o);
        if (tid == 0) red[0] = t;
    }
    __syncthreads();
    float inv = 1.0f / red[0];

    v0.x *= inv; v0.y *= inv; v0.z *= inv; v0.w *= inv;
    v1.x *= inv; v1.y *= inv; v1.z *= inv; v1.w *= inv;
    p4[tid] = v0; p4[tid + 256] = v1;
}

// ===========================================================================
extern "C" void kernel_launch(void* const* d_in, const int* in_sizes, int n_in,
                              void* d_out, int out_size)
{
    const float* q  = (const float*)d_in[0];
    const float* k  = (const float*)d_in[1];
    const float* v  = (const float*)d_in[2];
    const float* wq = (const float*)d_in[3];
    const float* wk = (const float*)d_in[4];
    const float* wv = (const float*)d_in[5];
    const float* wo = (const float*)d_in[6];

    float* out = (float*)d_out;
    const size_t OUT_ELEMS = (size_t)BB * LL * DM;

    float *gQ, *gK, *gVT, *gCtx;
    __nv_bfloat16 *gXH, *gXL, *gWTH, *gWTL;
    cudaGetSymbolAddress((void**)&gQ, g_Q);
    cudaGetSymbolAddress((void**)&gK, g_K);
    cudaGetSymbolAddress((void**)&gVT, g_VT);
    cudaGetSymbolAddress((void**)&gCtx, g_ctx);
    cudaGetSymbolAddress((void**)&gXH, g_XH);
    cudaGetSymbolAddress((void**)&gXL, g_XL);
    cudaGetSymbolAddress((void**)&gWTH, g_WTH);
    cudaGetSymbolAddress((void**)&gWTL, g_WTL);

    float* attn = out + OUT_ELEMS;

    const int N4 = (int)(OUT_ELEMS / 4);  // 2,097,152 float4s
    const int proj_smem = 34816;
    cudaFuncSetAttribute(proj_v2, cudaFuncAttributeMaxDynamicSharedMemorySize, proj_smem);
    const int out_smem = 34816;
    cudaFuncSetAttribute(out_v2, cudaFuncAttributeMaxDynamicSharedMemorySize, out_smem);

    // Q projection
    transsplit<<<dim3(2, 32, 16), dim3(256)>>>(wq, gWTH, gWTL, DM, DHEAD);
    presplit<<<dim3(8192), dim3(256)>>>((const float4*)q, (uint2*)gXH, (uint2*)gXL, N4);
    proj_v2<<<dim3(LL / 128, HH, BB), dim3(256), proj_smem>>>(gXH, gXL, gWTH, gWTL, gQ, nullptr, 0);

    // K projection
    transsplit<<<dim3(2, 32, 16), dim3(256)>>>(wk, gWTH, gWTL, DM, DHEAD);
    presplit<<<dim3(8192), dim3(256)>>>((const float4*)k, (uint2*)gXH, (uint2*)gXL, N4);
    proj_v2<<<dim3(LL / 128, HH, BB), dim3(256), proj_smem>>>(gXH, gXL, gWTH, gWTL, gK, nullptr, 0);

    // V projection (-> V^T fp32)
    transsplit<<<dim3(2, 32, 16), dim3(256)>>>(wv, gWTH, gWTL, DM, DHEAD);
    presplit<<<dim3(8192), dim3(256)>>>((const float4*)v, (uint2*)gXH, (uint2*)gXL, N4);
    proj_v2<<<dim3(LL / 128, HH, BB), dim3(256), proj_smem>>>(gXH, gXL, gWTH, gWTL, nullptr, gVT, 1);

    const int score_smem = 69632;
    cudaFuncSetAttribute(score_mma, cudaFuncAttributeMaxDynamicSharedMemorySize, score_smem);
    score_mma<<<dim3(LL / 128, LL / 128, NZ), dim3(512), score_smem>>>(gQ, gK, attn);

    softmax_kernel<<<dim3(NZ * LL), dim3(256)>>>(attn);

    const int ctx_smem = 52224;
    cudaFuncSetAttribute(ctx_mma, cudaFuncAttributeMaxDynamicSharedMemorySize, ctx_smem);
    ctx_mma<<<dim3(LL / 128, NZ), dim3(512), ctx_smem>>>(attn, gVT, gCtx);

    // Output GEMM: pre-split ctx (reuse X plane buffers) + transposed-split wo
    presplit<<<dim3(8192), dim3(256)>>>((const float4*)gCtx, (uint2*)gXH, (uint2*)gXL, N4);
    transsplit<<<dim3(32, 32, 1), dim3(256)>>>(wo, gWTH, gWTL, DM, DM);
    out_v2<<<dim3(DM / 64, (BB * LL) / 128), dim3(256), out_smem>>>(gXH, gXL, gWTH, gWTL, out);
}